// round 16
// baseline (speedup 1.0000x reference)
#include <cuda_runtime.h>
#include <cuda_fp16.h>
#include <math.h>
#include <stdint.h>

#define BATCH 16384
#define NJ 16
#define HID 128
#define MROWS (BATCH*NJ)

__constant__ unsigned int c_maskrow[16] = {
    0x0093u, 0x0007u, 0x000Eu, 0x000Cu,
    0x0031u, 0x0070u, 0x0060u, 0x0181u,
    0x4B80u, 0x0700u, 0x0600u, 0x1900u,
    0x3800u, 0x3000u, 0xC100u, 0xC000u
};

__device__ float g_h[MROWS * HID];
__device__ __half g_Xh0[MROWS * HID];
__device__ __half g_Xl0[MROWS * HID];
__device__ __half g_Xh1[MROWS * HID];
__device__ __half g_Xl1[MROWS * HID];
__device__ float g_d[10][16];
__device__ float g_Aoff[10][16][16];
__device__ int   g_adjidx[16][4];
__device__ float g_adjval[10][16][4];
__device__ float g_scale[9][HID];
__device__ float g_shift[9][HID];
// weight fragments: [l][sc=8][plane=2][n8=32][lane=32][4 halves]  (N=256 = [W0|W1])
__device__ __half g_Bfrag[8 * 8 * 2 * 32 * 32 * 4];

__device__ __forceinline__ void mma16816(float* c, const uint32_t* a,
                                         uint32_t b0, uint32_t b1) {
    asm volatile(
        "mma.sync.aligned.m16n8k16.row.col.f32.f16.f16.f32 "
        "{%0,%1,%2,%3},{%4,%5,%6,%7},{%8,%9},{%0,%1,%2,%3};"
        : "+f"(c[0]), "+f"(c[1]), "+f"(c[2]), "+f"(c[3])
        : "r"(a[0]), "r"(a[1]), "r"(a[2]), "r"(a[3]), "r"(b0), "r"(b1));
}
__device__ __forceinline__ void ldm4(uint32_t* d, uint32_t sa) {
    asm volatile("ldmatrix.sync.aligned.m8n8.x4.shared.b16 {%0,%1,%2,%3}, [%4];"
                 : "=r"(d[0]), "=r"(d[1]), "=r"(d[2]), "=r"(d[3]) : "r"(sa));
}
__device__ __forceinline__ void lds64(uint32_t& a, uint32_t& b, uint32_t sa) {
    asm volatile("ld.shared.v2.b32 {%0,%1}, [%2];" : "=r"(a), "=r"(b) : "r"(sa));
}
__device__ __forceinline__ void cp16(void* sdst, const void* g) {
    uint32_t sa = (uint32_t)__cvta_generic_to_shared(sdst);
    asm volatile("cp.async.cg.shared.global [%0], [%1], 16;" :: "r"(sa), "l"(g) : "memory");
}
#define CP_COMMIT() asm volatile("cp.async.commit_group;" ::: "memory")
#define CP_WAIT0()  asm volatile("cp.async.wait_group 0;" ::: "memory")

// ---------------- prep ----------------
__global__ void prep_kernel(const float* __restrict__ e_in,
                            const float* __restrict__ bn_in,
                            const float* __restrict__ b_in,
                            const float* __restrict__ e_mid,
                            const float* __restrict__ bn_mid,
                            const float* __restrict__ b_mid,
                            const float* __restrict__ e_out) {
    int t = threadIdx.x;
    if (t < 160) {
        int l = t >> 4, i = t & 15;
        const float* e = (l == 0) ? e_in : ((l <= 8) ? (e_mid + (l - 1) * 256) : e_out);
        unsigned int m = c_maskrow[i];
        float mx = -3.4e38f;
        for (int j = 0; j < 16; j++)
            if ((m >> j) & 1u) mx = fmaxf(mx, e[i * 16 + j]);
        float a[16]; float s = 0.f;
        for (int j = 0; j < 16; j++) {
            float v = ((m >> j) & 1u) ? expf(e[i * 16 + j] - mx) : 0.f;
            a[j] = v; s += v;
        }
        float inv = 1.f / s;
        g_d[l][i] = a[i] * inv;
        for (int j = 0; j < 16; j++)
            g_Aoff[l][i][j] = (j == i) ? 0.f : a[j] * inv;
        int idxs[4] = {i, i, i, i};
        float vals[4] = {0.f, 0.f, 0.f, 0.f};
        int cnt = 0;
        for (int j = 0; j < 16; j++) {
            if (j != i && ((m >> j) & 1u)) {
                idxs[cnt] = j; vals[cnt] = a[j] * inv; cnt++;
            }
        }
        for (int q = 0; q < 4; q++) g_adjval[l][i][q] = vals[q];
        if (l == 0)
            for (int q = 0; q < 4; q++) g_adjidx[i][q] = idxs[q];
    }
    for (int idx = t; idx < 9 * HID; idx += blockDim.x) {
        int lb = idx >> 7, f = idx & 127;
        float gamma, beta, mean, var, bias;
        if (lb == 0) {
            gamma = bn_in[f]; beta = bn_in[128 + f];
            mean = bn_in[256 + f]; var = bn_in[384 + f];
            bias = b_in[f];
        } else {
            const float* base = bn_mid + (lb - 1) * 512;
            gamma = base[f]; beta = base[128 + f];
            mean = base[256 + f]; var = base[384 + f];
            bias = b_mid[(lb - 1) * 128 + f];
        }
        float sc = gamma * rsqrtf(var + 1e-5f);
        g_scale[lb][f] = sc;
        g_shift[lb][f] = beta - mean * sc + bias * sc;
    }
}

// weight fragment shuffle: N=256 = [W0|W1], hi/lo planes
__global__ void wprep_kernel(const float* __restrict__ Wmid) {
    int idx = blockIdx.x * blockDim.x + threadIdx.x;
    if (idx >= 8 * 8 * 2 * 32 * 32) return;
    int lane = idx & 31;
    int n8 = (idx >> 5) & 31;
    int plane = (idx >> 10) & 1;
    int sc = (idx >> 11) & 7;
    int l = idx >> 14;
    int n = n8 * 8 + (lane >> 2);
    int sel = (n >= 128) ? 1 : 0;
    int col = n & 127;
    __half out[4];
#pragma unroll
    for (int r = 0; r < 2; r++)
#pragma unroll
        for (int h = 0; h < 2; h++) {
            int kl = (lane & 3) * 2 + h + r * 8;
            int kk = sc * 16 + kl;
            float v = Wmid[((l * 2 + sel) * 128 + kk) * 128 + col];
            __half hi = __float2half_rn(v);
            out[r * 2 + h] = plane ? __float2half_rn(v - __half2float(hi)) : hi;
        }
    *(uint64_t*)&g_Bfrag[(size_t)idx * 4] = *(uint64_t*)out;
}

// ---------------- input layer: h + hi/lo planes for L1 ----------------
__global__ void __launch_bounds__(256) in_kernel(const float* __restrict__ x,
                                                 const float* __restrict__ Win) {
    __shared__ float xs[128][2];
    __shared__ float sA[16][16];
    __shared__ float sdv[16];
    __shared__ float scl[128], shf[128];
    const int t = threadIdx.x;
    const int m0 = blockIdx.x * 128;
    sA[t >> 4][t & 15] = g_Aoff[0][t >> 4][t & 15];
    if (t < 16) sdv[t] = g_d[0][t];
    if (t < 128) { scl[t] = g_scale[0][t]; shf[t] = g_shift[0][t]; }
    ((float*)xs)[t] = x[m0 * 2 + t];
    __syncthreads();
    const int f = t & 127, gh = t >> 7;
    float w00 = Win[f], w01 = Win[128 + f], w10 = Win[256 + f], w11 = Win[384 + f];
    float sc = scl[f], sh = shf[f];
    for (int gg = 0; gg < 4; gg++) {
        int g = gh * 4 + gg;
        float q[16];
#pragma unroll
        for (int j = 0; j < 16; j++)
            q[j] = xs[16 * g + j][0] * w10 + xs[16 * g + j][1] * w11;
#pragma unroll
        for (int i = 0; i < 16; i++) {
            float o = sdv[i] * (xs[16 * g + i][0] * w00 + xs[16 * g + i][1] * w01);
#pragma unroll
            for (int j = 0; j < 16; j++) o += sA[i][j] * q[j];
            o = fmaxf(o * sc + sh, 0.f);
            size_t idx = (size_t)(m0 + 16 * g + i) * HID + f;
            g_h[idx] = o;
            __half hh = __float2half_rn(o);
            g_Xh0[idx] = hh;
            g_Xl0[idx] = __float2half_rn(o - __half2float(hh));
        }
    }
}

// ---------------- mid layer: postmix GEMM X·[W0|W1], M=128 N=256 K=128 ----------------
#define A_STR 24
struct MidSm {
    union {
        struct {
            __half Axh[2][128][A_STR];   // 12288 B
            __half Axl[2][128][A_STR];   // 12288 B
            __half Bs[2][2][32][32][4];  // 32768 B
        } m;
        float Ps[128][132];              // 67584 B
    } u;
    float sAv[16][4];
    int   sAi[16][4];
    float sd[16];
    float scl[128], shf[128];
};

__device__ __forceinline__ void issueA(MidSm& S, int buf, const __half* Xh,
                                       const __half* Xl, int m0, int sc, int t) {
    int plane = t >> 8;          // 0..1
    int row = (t >> 1) & 127;
    int seg = t & 1;
    const __half* src = (plane ? Xl : Xh) + (size_t)(m0 + row) * HID + sc * 16 + seg * 8;
    __half* dst = plane ? &S.u.m.Axl[buf][row][seg * 8] : &S.u.m.Axh[buf][row][seg * 8];
    cp16(dst, src);
}
__device__ __forceinline__ void issueB(MidSm& S, int buf, const __half* Bf,
                                       int sc, int t) {
#pragma unroll
    for (int i = 0; i < 2; i++) {
        int u = t + i * 512;     // 0..1023
        cp16(((char*)S.u.m.Bs) + buf * 16384 + u * 16, Bf + (size_t)sc * 8192 + (size_t)u * 8);
    }
}

__global__ void __launch_bounds__(512, 1)
mid_mma(const __half* __restrict__ Xh, const __half* __restrict__ Xl,
        __half* __restrict__ Yh, __half* __restrict__ Yl,
        float* __restrict__ Hraw, const __half* __restrict__ Bf,
        int layer, int flags) {
    extern __shared__ __align__(16) char smraw[];
    MidSm& S = *reinterpret_cast<MidSm*>(smraw);
    const int t = threadIdx.x, lane = t & 31, warp = t >> 5;
    const int wm = warp >> 2, wn = warp & 3;   // 4 m-warps x 4 n-warps
    const int m0 = blockIdx.x * 128;

    if (t < 64) S.sAv[t >> 2][t & 3] = g_adjval[layer][t >> 2][t & 3];
    else if (t < 128) { int u = t - 64; S.sAi[u >> 2][u & 3] = g_adjidx[u >> 2][u & 3]; }
    else if (t < 144) S.sd[t - 128] = g_d[layer][t - 128];
    if (t >= 256 && t < 384) S.scl[t - 256] = g_scale[layer][t - 256];
    else if (t >= 384) S.shf[t - 384] = g_shift[layer][t - 384];

    issueA(S, 0, Xh, Xl, m0, 0, t);
    issueB(S, 0, Bf, 0, t);
    CP_COMMIT();
    CP_WAIT0();
    __syncthreads();

    float acc[2][8][4];
#pragma unroll
    for (int a = 0; a < 2; a++)
#pragma unroll
        for (int b = 0; b < 8; b++)
#pragma unroll
            for (int c = 0; c < 4; c++) acc[a][b][c] = 0.f;

    const uint32_t smbase = (uint32_t)__cvta_generic_to_shared(&S);
    const uint32_t AlOff = 12288u;
    const uint32_t BsOff = 24576u;

#pragma unroll 1
    for (int sc = 0; sc < 8; sc++) {
        if (sc < 7) {
            issueA(S, (sc + 1) & 1, Xh, Xl, m0, sc + 1, t);
            issueB(S, (sc + 1) & 1, Bf, sc + 1, t);
            CP_COMMIT();
        }
        const int buf = sc & 1;
        uint32_t ah[2][4], al[2][4];
        {
            int lr = lane & 7, sel = lane >> 3;
            int rofs = (sel & 1) * 8 + lr, cofs = (sel >> 1) * 8;
#pragma unroll
            for (int mf = 0; mf < 2; mf++) {
                int row = wm * 32 + mf * 16 + rofs;
                uint32_t ao = (uint32_t)((buf * 128 + row) * A_STR + cofs) * 2;
                ldm4(ah[mf], smbase + ao);
                ldm4(al[mf], smbase + AlOff + ao);
            }
        }
#pragma unroll
        for (int nf = 0; nf < 8; nf++) {
            uint32_t bb = smbase + BsOff + (uint32_t)buf * 16384 +
                          (uint32_t)(wn * 8 + nf) * 256 + (uint32_t)lane * 8;
            uint32_t bh0, bh1, bl0, bl1;
            lds64(bh0, bh1, bb);
            lds64(bl0, bl1, bb + 8192);
#pragma unroll
            for (int mf = 0; mf < 2; mf++) {
                mma16816(acc[mf][nf], ah[mf], bh0, bh1);
                mma16816(acc[mf][nf], al[mf], bh0, bh1);
                mma16816(acc[mf][nf], ah[mf], bl0, bl1);
            }
        }
        if (sc < 7) CP_WAIT0();
        __syncthreads();
    }

    // ---- epilogue: stage P1 (wn>=2), then postmix + bn_relu + residual + split (wn<2) ----
    const bool doRes = (flags & 1) != 0;
    const bool doPlanes = (flags & 2) != 0;
    if (wn >= 2) {
#pragma unroll
        for (int mf = 0; mf < 2; mf++) {
            int lr0 = wm * 32 + mf * 16 + (lane >> 2);
#pragma unroll
            for (int nf = 0; nf < 8; nf++) {
                int c = (wn - 2) * 64 + nf * 8 + (lane & 3) * 2;
                float2 v0; v0.x = acc[mf][nf][0]; v0.y = acc[mf][nf][1];
                float2 v1; v1.x = acc[mf][nf][2]; v1.y = acc[mf][nf][3];
                *(float2*)&S.u.Ps[lr0][c] = v0;
                *(float2*)&S.u.Ps[lr0 + 8][c] = v1;
            }
        }
    }
    __syncthreads();
    if (wn < 2) {
        int i1 = lane >> 2, i2 = i1 + 8;
        int j1[4], j2[4];
        float v1[4], v2[4];
#pragma unroll
        for (int q = 0; q < 4; q++) {
            j1[q] = S.sAi[i1][q]; v1[q] = S.sAv[i1][q];
            j2[q] = S.sAi[i2][q]; v2[q] = S.sAv[i2][q];
        }
        float d1 = S.sd[i1], d2 = S.sd[i2];
#pragma unroll
        for (int mf = 0; mf < 2; mf++) {
            int rb = wm * 32 + mf * 16;
            int lr0 = rb + i1;
            size_t base = (size_t)(m0 + lr0) * HID;
#pragma unroll
            for (int nf = 0; nf < 8; nf++) {
                int cg = wn * 64 + nf * 8 + (lane & 3) * 2;
                float y00 = d1 * acc[mf][nf][0];
                float y01 = d1 * acc[mf][nf][1];
                float y10 = d2 * acc[mf][nf][2];
                float y11 = d2 * acc[mf][nf][3];
#pragma unroll
                for (int q = 0; q < 4; q++) {
                    const float* p1 = &S.u.Ps[rb + j1[q]][cg];
                    y00 += v1[q] * p1[0];
                    y01 += v1[q] * p1[1];
                    const float* p2 = &S.u.Ps[rb + j2[q]][cg];
                    y10 += v2[q] * p2[0];
                    y11 += v2[q] * p2[1];
                }
                float s0 = S.scl[cg], s1 = S.scl[cg + 1];
                float h0 = S.shf[cg], h1 = S.shf[cg + 1];
                y00 = fmaxf(y00 * s0 + h0, 0.f);
                y01 = fmaxf(y01 * s1 + h1, 0.f);
                y10 = fmaxf(y10 * s0 + h0, 0.f);
                y11 = fmaxf(y11 * s1 + h1, 0.f);
                if (doRes) {
                    float2 r0v = *(const float2*)&Hraw[base + cg];
                    float2 r1v = *(const float2*)&Hraw[base + 8 * HID + cg];
                    y00 += r0v.x; y01 += r0v.y;
                    y10 += r1v.x; y11 += r1v.y;
                    float2 w0; w0.x = y00; w0.y = y01;
                    float2 w1; w1.x = y10; w1.y = y11;
                    *(float2*)&Hraw[base + cg] = w0;
                    *(float2*)&Hraw[base + 8 * HID + cg] = w1;
                }
                if (doPlanes) {
                    __half h00 = __float2half_rn(y00), h01 = __float2half_rn(y01);
                    __half h10 = __float2half_rn(y10), h11 = __float2half_rn(y11);
                    __half2 ph0; ph0.x = h00; ph0.y = h01;
                    __half2 ph1; ph1.x = h10; ph1.y = h11;
                    *(__half2*)&Yh[base + cg] = ph0;
                    *(__half2*)&Yh[base + 8 * HID + cg] = ph1;
                    __half2 pl0, pl1;
                    pl0.x = __float2half_rn(y00 - __half2float(h00));
                    pl0.y = __float2half_rn(y01 - __half2float(h01));
                    pl1.x = __float2half_rn(y10 - __half2float(h10));
                    pl1.y = __float2half_rn(y11 - __half2float(h11));
                    *(__half2*)&Yl[base + cg] = pl0;
                    *(__half2*)&Yl[base + 8 * HID + cg] = pl1;
                }
            }
        }
    }
}

// ---------------- output layer + MDN (unchanged from R14) ----------------
struct OutSm {
    float hs[64][132];
    float2 Ws2[128][26];
    float P1[64][26];
    float sA[16][16];
    float sdv[16];
    float bo[25];
};

__device__ __forceinline__ unsigned long long pack2o(float x, float y) {
    unsigned long long r;
    asm("mov.b64 %0, {%1,%2};" : "=l"(r) : "f"(x), "f"(y));
    return r;
}
__device__ __forceinline__ void unpack2o(unsigned long long v, float &x, float &y) {
    asm("mov.b64 {%0,%1}, %2;" : "=f"(x), "=f"(y) : "l"(v));
}
__device__ __forceinline__ unsigned long long ffma2o(unsigned long long a,
                                                     unsigned long long b,
                                                     unsigned long long c) {
    unsigned long long d;
    asm("fma.rn.f32x2 %0, %1, %2, %3;" : "=l"(d) : "l"(a), "l"(b), "l"(c));
    return d;
}

__global__ void __launch_bounds__(256) out_kernel(const float* __restrict__ Wout,
                                                  const float* __restrict__ bout,
                                                  float* __restrict__ out) {
    extern __shared__ __align__(16) char osmraw[];
    OutSm& S = *reinterpret_cast<OutSm*>(osmraw);
    const int t = threadIdx.x;
    const int m0 = blockIdx.x * 64;
    S.sA[t >> 4][t & 15] = g_Aoff[9][t >> 4][t & 15];
    if (t < 16) S.sdv[t] = g_d[9][t];
    if (t < 25) S.bo[t] = bout[t];
    for (int idx = t; idx < 2048; idx += 256) {
        int r = idx >> 5, q = idx & 31;
        *(float4*)&S.hs[r][q * 4] = *(const float4*)&g_h[(size_t)(m0 + r) * HID + q * 4];
    }
    for (int idx = t; idx < 6400; idx += 256) {
        int s = idx / 3200, rr = idx - s * 3200;
        int k = rr / 25, c = rr - k * 25;
        ((float*)&S.Ws2[k][c])[s] = Wout[idx];
    }
    __syncthreads();
    const int r = t >> 2, cs = t & 3;
    const int i = r & 15, rb = r & ~15;
    int cols[7]; int nc = 0;
    for (int c = cs; c < 25; c += 4) { cols[nc] = c; nc++; }
    unsigned long long pp[7];
#pragma unroll
    for (int q = 0; q < 7; q++) pp[q] = pack2o(0.f, 0.f);
    for (int k = 0; k < HID; k++) {
        float h = S.hs[r][k];
        unsigned long long hp = pack2o(h, h);
#pragma unroll
        for (int q = 0; q < 7; q++)
            if (q < nc)
                pp[q] = ffma2o(hp, *(const unsigned long long*)&S.Ws2[k][cols[q]], pp[q]);
    }
    float p0[7];
    for (int q = 0; q < nc; q++) {
        float a, b;
        unpack2o(pp[q], a, b);
        p0[q] = a;
        S.P1[r][cols[q]] = b;
    }
    __syncthreads();
    float d = S.sdv[i];
    for (int q = 0; q < nc; q++) {
        int c = cols[q];
        float o = d * p0[q] + S.bo[c];
#pragma unroll
        for (int j = 0; j < 16; j++) o += S.sA[i][j] * S.P1[rb + j][c];
        int row = m0 + r;
        if (c < 15) {
            out[(size_t)row * 15 + c] = tanhf(o);
        } else if (c < 20) {
            float sg = (o > 0.f) ? (o + 1.f) : expf(o);
            out[(size_t)MROWS * 15 + (size_t)row * 5 + (c - 15)] = fmaxf(sg, 1e-10f);
        } else {
            out[(size_t)MROWS * 20 + (size_t)row * 5 + (c - 20)] = o;
        }
    }
}

extern "C" void kernel_launch(void* const* d_in, const int* in_sizes, int n_in,
                              void* d_out, int out_size) {
    const float* x      = (const float*)d_in[0];
    const float* W_in   = (const float*)d_in[1];
    const float* e_in   = (const float*)d_in[2];
    const float* b_in   = (const float*)d_in[3];
    const float* bn_in  = (const float*)d_in[4];
    const float* W_mid  = (const float*)d_in[5];
    const float* e_mid  = (const float*)d_in[6];
    const float* b_mid  = (const float*)d_in[7];
    const float* bn_mid = (const float*)d_in[8];
    const float* W_out  = (const float*)d_in[9];
    const float* e_out  = (const float*)d_in[10];
    const float* b_out  = (const float*)d_in[11];
    float* out = (float*)d_out;

    static int smem_set = 0;
    if (!smem_set) {
        cudaFuncSetAttribute(mid_mma, cudaFuncAttributeMaxDynamicSharedMemorySize,
                             (int)sizeof(MidSm));
        cudaFuncSetAttribute(out_kernel, cudaFuncAttributeMaxDynamicSharedMemorySize,
                             (int)sizeof(OutSm));
        smem_set = 1;
    }

    prep_kernel<<<1, 256>>>(e_in, bn_in, b_in, e_mid, bn_mid, b_mid, e_out);
    wprep_kernel<<<512, 256>>>(W_mid);
    in_kernel<<<2048, 256>>>(x, W_in);

    __half *xh0, *xl0, *xh1, *xl1, *bfh;
    float* gh;
    cudaGetSymbolAddress((void**)&xh0, g_Xh0);
    cudaGetSymbolAddress((void**)&xl0, g_Xl0);
    cudaGetSymbolAddress((void**)&xh1, g_Xh1);
    cudaGetSymbolAddress((void**)&xl1, g_Xl1);
    cudaGetSymbolAddress((void**)&bfh, g_Bfrag);
    cudaGetSymbolAddress((void**)&gh, g_h);

    for (int L = 1; L <= 8; L++) {
        const __half* sh = (L & 1) ? xh0 : xh1;
        const __half* sl = (L & 1) ? xl0 : xl1;
        __half* dh = (L & 1) ? xh1 : xh0;
        __half* dl = (L & 1) ? xl1 : xl0;
        int flags = (((L & 1) == 0) ? 1 : 0) | ((L < 8) ? 2 : 0);
        mid_mma<<<2048, 512, sizeof(MidSm)>>>(sh, sl, dh, dl, gh,
                                              bfh + (size_t)(L - 1) * 65536, L, flags);
    }
    out_kernel<<<MROWS / 64, 256, sizeof(OutSm)>>>(W_out, b_out, out);
}

// round 17
// speedup vs baseline: 1.4215x; 1.4215x over previous
#include <cuda_runtime.h>
#include <cuda_fp16.h>
#include <math.h>
#include <stdint.h>

#define BATCH 16384
#define NJ 16
#define HID 128
#define MROWS (BATCH*NJ)

__constant__ unsigned int c_maskrow[16] = {
    0x0093u, 0x0007u, 0x000Eu, 0x000Cu,
    0x0031u, 0x0070u, 0x0060u, 0x0181u,
    0x4B80u, 0x0700u, 0x0600u, 0x1900u,
    0x3800u, 0x3000u, 0xC100u, 0xC000u
};

__device__ float g_h[MROWS * HID];
__device__ float g_t[MROWS * HID];
__device__ float g_d[10][16];
__device__ float g_Aoff[10][16][16];
__device__ int   g_adjidx[16][4];
__device__ float g_adjval[10][16][4];
__device__ float g_scale[9][HID];
__device__ float g_shift[9][HID];
// weight fragments: [l][sc=8][pair=2][plane=2][n8=16][lane=32][4 halves]
__device__ __half g_Bfrag[8 * 8 * 2 * 2 * 16 * 32 * 4];

__device__ __forceinline__ unsigned long long pack2(float x, float y) {
    unsigned long long r;
    asm("mov.b64 %0, {%1,%2};" : "=l"(r) : "f"(x), "f"(y));
    return r;
}
__device__ __forceinline__ void unpack2(unsigned long long v, float &x, float &y) {
    asm("mov.b64 {%0,%1}, %2;" : "=f"(x), "=f"(y) : "l"(v));
}
__device__ __forceinline__ unsigned long long ffma2(unsigned long long a,
                                                    unsigned long long b,
                                                    unsigned long long c) {
    unsigned long long d;
    asm("fma.rn.f32x2 %0, %1, %2, %3;" : "=l"(d) : "l"(a), "l"(b), "l"(c));
    return d;
}
__device__ __forceinline__ void mma16816(float* c, const uint32_t* a,
                                         uint32_t b0, uint32_t b1) {
    asm volatile(
        "mma.sync.aligned.m16n8k16.row.col.f32.f16.f16.f32 "
        "{%0,%1,%2,%3},{%4,%5,%6,%7},{%8,%9},{%0,%1,%2,%3};"
        : "+f"(c[0]), "+f"(c[1]), "+f"(c[2]), "+f"(c[3])
        : "r"(a[0]), "r"(a[1]), "r"(a[2]), "r"(a[3]), "r"(b0), "r"(b1));
}
__device__ __forceinline__ void ldm4(uint32_t* d, uint32_t sa) {
    asm volatile("ldmatrix.sync.aligned.m8n8.x4.shared.b16 {%0,%1,%2,%3}, [%4];"
                 : "=r"(d[0]), "=r"(d[1]), "=r"(d[2]), "=r"(d[3]) : "r"(sa));
}
__device__ __forceinline__ void lds64(uint32_t& a, uint32_t& b, uint32_t sa) {
    asm volatile("ld.shared.v2.b32 {%0,%1}, [%2];" : "=r"(a), "=r"(b) : "r"(sa));
}
__device__ __forceinline__ void cp16(void* sdst, const void* g) {
    uint32_t sa = (uint32_t)__cvta_generic_to_shared(sdst);
    asm volatile("cp.async.cg.shared.global [%0], [%1], 16;" :: "r"(sa), "l"(g) : "memory");
}
#define CP_COMMIT() asm volatile("cp.async.commit_group;" ::: "memory")
#define CP_WAIT0()  asm volatile("cp.async.wait_group 0;" ::: "memory")

// ---------------- prep ----------------
__global__ void prep_kernel(const float* __restrict__ e_in,
                            const float* __restrict__ bn_in,
                            const float* __restrict__ b_in,
                            const float* __restrict__ e_mid,
                            const float* __restrict__ bn_mid,
                            const float* __restrict__ b_mid,
                            const float* __restrict__ e_out) {
    int t = threadIdx.x;
    if (t < 160) {
        int l = t >> 4, i = t & 15;
        const float* e = (l == 0) ? e_in : ((l <= 8) ? (e_mid + (l - 1) * 256) : e_out);
        unsigned int m = c_maskrow[i];
        float mx = -3.4e38f;
        for (int j = 0; j < 16; j++)
            if ((m >> j) & 1u) mx = fmaxf(mx, e[i * 16 + j]);
        float a[16]; float s = 0.f;
        for (int j = 0; j < 16; j++) {
            float v = ((m >> j) & 1u) ? expf(e[i * 16 + j] - mx) : 0.f;
            a[j] = v; s += v;
        }
        float inv = 1.f / s;
        g_d[l][i] = a[i] * inv;
        for (int j = 0; j < 16; j++)
            g_Aoff[l][i][j] = (j == i) ? 0.f : a[j] * inv;
        int idxs[4] = {i, i, i, i};
        float vals[4] = {0.f, 0.f, 0.f, 0.f};
        int cnt = 0;
        for (int j = 0; j < 16; j++) {
            if (j != i && ((m >> j) & 1u)) {
                idxs[cnt] = j; vals[cnt] = a[j] * inv; cnt++;
            }
        }
        for (int q = 0; q < 4; q++) g_adjval[l][i][q] = vals[q];
        if (l == 0)
            for (int q = 0; q < 4; q++) g_adjidx[i][q] = idxs[q];
    }
    for (int idx = t; idx < 9 * HID; idx += blockDim.x) {
        int lb = idx >> 7, f = idx & 127;
        float gamma, beta, mean, var, bias;
        if (lb == 0) {
            gamma = bn_in[f]; beta = bn_in[128 + f];
            mean = bn_in[256 + f]; var = bn_in[384 + f];
            bias = b_in[f];
        } else {
            const float* base = bn_mid + (lb - 1) * 512;
            gamma = base[f]; beta = base[128 + f];
            mean = base[256 + f]; var = base[384 + f];
            bias = b_mid[(lb - 1) * 128 + f];
        }
        float sc = gamma * rsqrtf(var + 1e-5f);
        g_scale[lb][f] = sc;
        g_shift[lb][f] = beta - mean * sc + bias * sc;
    }
}

// weight fragment shuffle
__global__ void wprep_kernel(const float* __restrict__ Wmid) {
    int idx = blockIdx.x * blockDim.x + threadIdx.x;
    if (idx >= 8 * 8 * 2 * 2 * 16 * 32) return;
    int lane = idx & 31;
    int n8 = (idx >> 5) & 15;
    int plane = (idx >> 9) & 1;
    int pair = (idx >> 10) & 1;
    int sc = (idx >> 11) & 7;
    int l = idx >> 14;
    int n = n8 * 8 + (lane >> 2);
    int chunk = pair ? (sc + 8) : sc;
    __half out[4];
#pragma unroll
    for (int r = 0; r < 2; r++)
#pragma unroll
        for (int h = 0; h < 2; h++) {
            int klocal = (lane & 3) * 2 + h + r * 8;
            int kk = chunk * 16 + klocal;
            float v = (kk < 128) ? Wmid[((l * 2 + 0) * 128 + kk) * 128 + n]
                                 : Wmid[((l * 2 + 1) * 128 + (kk - 128)) * 128 + n];
            __half hi = __float2half_rn(v);
            out[r * 2 + h] = plane ? __float2half_rn(v - __half2float(hi)) : hi;
        }
    *(uint64_t*)&g_Bfrag[(size_t)idx * 4] = *(uint64_t*)out;
}

// ---------------- input layer (paired f32x2 accumulation) ----------------
__global__ void __launch_bounds__(256) in_kernel(const float* __restrict__ x,
                                                 const float* __restrict__ Win) {
    __shared__ float xs[128][2];
    __shared__ float sA[16][16];
    __shared__ float sdv[16];
    __shared__ float scl[128], shf[128];
    const int t = threadIdx.x;
    const int m0 = blockIdx.x * 128;
    sA[t >> 4][t & 15] = g_Aoff[0][t >> 4][t & 15];
    if (t < 16) sdv[t] = g_d[0][t];
    if (t < 128) { scl[t] = g_scale[0][t]; shf[t] = g_shift[0][t]; }
    ((float*)xs)[t] = x[m0 * 2 + t];
    __syncthreads();
    const int f = t & 127, gh = t >> 7;
    float w00 = Win[f], w01 = Win[128 + f], w10 = Win[256 + f], w11 = Win[384 + f];
    float sc = scl[f], sh = shf[f];
    for (int gp = 0; gp < 2; gp++) {
        int g1 = gh * 4 + gp * 2, g2 = g1 + 1;
        float q1[16], q2[16];
        unsigned long long qp[16];
#pragma unroll
        for (int j = 0; j < 16; j++) {
            q1[j] = xs[16 * g1 + j][0] * w10 + xs[16 * g1 + j][1] * w11;
            q2[j] = xs[16 * g2 + j][0] * w10 + xs[16 * g2 + j][1] * w11;
            qp[j] = pack2(q1[j], q2[j]);
        }
#pragma unroll
        for (int i = 0; i < 16; i++) {
            float o1 = sdv[i] * (xs[16 * g1 + i][0] * w00 + xs[16 * g1 + i][1] * w01);
            float o2 = sdv[i] * (xs[16 * g2 + i][0] * w00 + xs[16 * g2 + i][1] * w01);
            unsigned long long op = pack2(o1, o2);
#pragma unroll
            for (int j = 0; j < 16; j++) {
                float aij = sA[i][j];
                op = ffma2(pack2(aij, aij), qp[j], op);
            }
            unpack2(op, o1, o2);
            g_h[(size_t)(m0 + 16 * g1 + i) * HID + f] = fmaxf(o1 * sc + sh, 0.f);
            g_h[(size_t)(m0 + 16 * g2 + i) * HID + f] = fmaxf(o2 * sc + sh, 0.f);
        }
    }
}

// ---------------- mid layer: HMMA, A-double-buffered single-barrier pipeline (R14) ----------------
#define XS_STR 20
#define A_STR 24
struct MidSm {
    float Xs[2][128][XS_STR];
    __half Bs[2][2][2][16][32][4];
    __half Ah[2][2][128][A_STR];
    __half Al[2][2][128][A_STR];
    float sAv[16][4];
    int   sAi[16][4];
    float sd[16];
    float scl[128], shf[128];
};

__device__ __forceinline__ void issueX(MidSm& S, int xbuf, const float* X,
                                       int m0, int k0, int t) {
    int u0 = t, u1 = t + 256;
    cp16(&S.Xs[xbuf][u0 >> 2][(u0 & 3) * 4], X + (m0 + (u0 >> 2)) * HID + k0 + (u0 & 3) * 4);
    cp16(&S.Xs[xbuf][u1 >> 2][(u1 & 3) * 4], X + (m0 + (u1 >> 2)) * HID + k0 + (u1 & 3) * 4);
}
__device__ __forceinline__ void issueB(MidSm& S, int bbuf, const __half* Bf,
                                       int sc, int t) {
#pragma unroll
    for (int i = 0; i < 4; i++) {
        int u = t + i * 256;
        cp16(((char*)S.Bs[bbuf]) + u * 16, Bf + (size_t)sc * 8192 + (size_t)u * 8);
    }
}
__device__ __forceinline__ void premix(MidSm& S, int abuf, int xbuf, int t) {
    int r = t >> 1, kb = (t & 1) * 8;
    int i = r & 15, rb = r & ~15;
    float d = S.sd[i];
    const float* xrow = &S.Xs[xbuf][r][kb];
#pragma unroll
    for (int q = 0; q < 8; q++) {
        float u = d * xrow[q];
        __half uh = __float2half_rn(u);
        S.Ah[abuf][0][r][kb + q] = uh;
        S.Al[abuf][0][r][kb + q] = __float2half_rn(u - __half2float(uh));
    }
    unsigned long long vacc[4];
#pragma unroll
    for (int q = 0; q < 4; q++) vacc[q] = pack2(0.f, 0.f);
#pragma unroll
    for (int qj = 0; qj < 4; qj++) {
        float aij = S.sAv[i][qj];
        int j = S.sAi[i][qj];
        unsigned long long ap = pack2(aij, aij);
        const unsigned long long* xr = (const unsigned long long*)&S.Xs[xbuf][rb + j][kb];
#pragma unroll
        for (int q = 0; q < 4; q++) vacc[q] = ffma2(ap, xr[q], vacc[q]);
    }
#pragma unroll
    for (int q = 0; q < 4; q++) {
        float v0, v1; unpack2(vacc[q], v0, v1);
        __half h0 = __float2half_rn(v0), h1 = __float2half_rn(v1);
        S.Ah[abuf][1][r][kb + q * 2] = h0;
        S.Ah[abuf][1][r][kb + q * 2 + 1] = h1;
        S.Al[abuf][1][r][kb + q * 2] = __float2half_rn(v0 - __half2float(h0));
        S.Al[abuf][1][r][kb + q * 2 + 1] = __float2half_rn(v1 - __half2float(h1));
    }
}

__global__ void __launch_bounds__(256, 2)
mid_mma(const float* __restrict__ X, float* __restrict__ Y,
        const float* __restrict__ R, const __half* __restrict__ Bf, int layer) {
    extern __shared__ __align__(16) char smraw[];
    MidSm& S = *reinterpret_cast<MidSm*>(smraw);
    const int t = threadIdx.x, lane = t & 31, warp = t >> 5;
    const int wm = warp & 3, wn = warp >> 2;
    const int m0 = blockIdx.x * 128;

    if (t < 64) S.sAv[t >> 2][t & 3] = g_adjval[layer][t >> 2][t & 3];
    else if (t < 128) { int u = t - 64; S.sAi[u >> 2][u & 3] = g_adjidx[u >> 2][u & 3]; }
    if (t < 16) S.sd[t] = g_d[layer][t];
    if (t >= 128) { int f = t - 128; S.scl[f] = g_scale[layer][f]; S.shf[f] = g_shift[layer][f]; }

    issueX(S, 0, X, m0, 0, t);
    issueX(S, 1, X, m0, 16, t);
    issueB(S, 0, Bf, 0, t);
    CP_COMMIT();
    CP_WAIT0();
    __syncthreads();
    premix(S, 0, 0, t);
    __syncthreads();

    float acc[2][8][4];
#pragma unroll
    for (int a = 0; a < 2; a++)
#pragma unroll
        for (int b = 0; b < 8; b++)
#pragma unroll
            for (int c = 0; c < 4; c++) acc[a][b][c] = 0.f;

    const uint32_t smbase = (uint32_t)__cvta_generic_to_shared(&S);
    const uint32_t AhOff = (uint32_t)((char*)&S.Ah[0][0][0][0] - (char*)&S);
    const uint32_t AlOff = (uint32_t)((char*)&S.Al[0][0][0][0] - (char*)&S);
    const uint32_t BsOff = (uint32_t)((char*)&S.Bs[0][0][0][0][0][0] - (char*)&S);

#pragma unroll 1
    for (int sc = 0; sc < 8; sc++) {
        if (sc < 7) {
            if (sc < 6) issueX(S, sc & 1, X, m0, (sc + 2) * 16, t);
            issueB(S, (sc + 1) & 1, Bf, sc + 1, t);
            CP_COMMIT();
        }
        const int abuf = sc & 1;
#pragma unroll
        for (int pr = 0; pr < 2; pr++) {
            uint32_t ah[2][4], al[2][4];
            int lr = lane & 7, sel = lane >> 3;
            int rofs = (sel & 1) * 8 + lr, cofs = (sel >> 1) * 8;
#pragma unroll
            for (int mf = 0; mf < 2; mf++) {
                int row = wm * 32 + mf * 16 + rofs;
                uint32_t ao = (uint32_t)(((abuf * 2 + pr) * 128 + row) * A_STR + cofs) * 2;
                ldm4(ah[mf], smbase + AhOff + ao);
                ldm4(al[mf], smbase + AlOff + ao);
            }
#pragma unroll
            for (int nf = 0; nf < 8; nf++) {
                uint32_t bb = smbase + BsOff + (uint32_t)abuf * 16384 +
                              (uint32_t)pr * 8192 + (uint32_t)(wn * 8 + nf) * 256 +
                              (uint32_t)lane * 8;
                uint32_t bh0, bh1, bl0, bl1;
                lds64(bh0, bh1, bb);
                lds64(bl0, bl1, bb + 4096);
#pragma unroll
                for (int mf = 0; mf < 2; mf++) {
                    mma16816(acc[mf][nf], ah[mf], bh0, bh1);
                    mma16816(acc[mf][nf], al[mf], bh0, bh1);
                    mma16816(acc[mf][nf], ah[mf], bl0, bl1);
                }
            }
        }
        if (sc < 7) {
            premix(S, abuf ^ 1, (sc + 1) & 1, t);
            CP_WAIT0();
        }
        __syncthreads();
    }
    // epilogue
#pragma unroll
    for (int mf = 0; mf < 2; mf++) {
        int r0 = m0 + wm * 32 + mf * 16 + (lane >> 2);
#pragma unroll
        for (int nf = 0; nf < 8; nf++) {
            int cg = wn * 64 + nf * 8 + (lane & 3) * 2;
            float s0 = S.scl[cg], s1 = S.scl[cg + 1];
            float h0 = S.shf[cg], h1 = S.shf[cg + 1];
            float y0 = fmaxf(acc[mf][nf][0] * s0 + h0, 0.f);
            float y1 = fmaxf(acc[mf][nf][1] * s1 + h1, 0.f);
            float y2 = fmaxf(acc[mf][nf][2] * s0 + h0, 0.f);
            float y3 = fmaxf(acc[mf][nf][3] * s1 + h1, 0.f);
            if (R) {
                y0 += R[r0 * HID + cg];       y1 += R[r0 * HID + cg + 1];
                y2 += R[(r0 + 8) * HID + cg]; y3 += R[(r0 + 8) * HID + cg + 1];
            }
            float2 v0; v0.x = y0; v0.y = y1;
            float2 v1; v1.x = y2; v1.y = y3;
            *(float2*)&Y[r0 * HID + cg] = v0;
            *(float2*)&Y[(r0 + 8) * HID + cg] = v1;
        }
    }
}

// ---------------- output layer + MDN: 128 rows/CTA, 4-row tiling ----------------
struct OutSm {
    union {
        float hs[128][132];    // 67584 B (main loop)
        float P1[128][26];     // 13312 B (postmix)
    } u;
    float2 Ws2[128][26];       // 26624 B
    float sAv[16][4];
    int   sAi[16][4];
    float sdv[16];
    float bo[25];
};

__global__ void __launch_bounds__(256, 2) out_kernel(const float* __restrict__ Wout,
                                                     const float* __restrict__ bout,
                                                     float* __restrict__ out) {
    extern __shared__ __align__(16) char osmraw[];
    OutSm& S = *reinterpret_cast<OutSm*>(osmraw);
    const int t = threadIdx.x;
    const int m0 = blockIdx.x * 128;
    if (t < 64) S.sAv[t >> 2][t & 3] = g_adjval[9][t >> 2][t & 3];
    else if (t < 128) { int u = t - 64; S.sAi[u >> 2][u & 3] = g_adjidx[u >> 2][u & 3]; }
    if (t < 16) S.sdv[t] = g_d[9][t];
    if (t >= 128 && t < 153) S.bo[t - 128] = bout[t - 128];
    for (int idx = t; idx < 4096; idx += 256) {
        int r = idx >> 5, q = idx & 31;
        *(float4*)&S.u.hs[r][q * 4] = *(const float4*)&g_h[(size_t)(m0 + r) * HID + q * 4];
    }
    for (int idx = t; idx < 6400; idx += 256) {
        int s = idx / 3200, rr = idx - s * 3200;
        int k = rr / 25, c = rr - k * 25;
        ((float*)&S.Ws2[k][c])[s] = Wout[idx];
    }
    __syncthreads();

    const int rg = t >> 3, cs = t & 7;     // 32 row-groups x 8 col-slots
    const int r0 = rg * 4;
    int cols[4]; int nc = 0;
    for (int c = cs; c < 25; c += 8) { cols[nc] = c; nc++; }   // <=4

    unsigned long long acc[4][4];
#pragma unroll
    for (int rr = 0; rr < 4; rr++)
#pragma unroll
        for (int q = 0; q < 4; q++) acc[rr][q] = pack2(0.f, 0.f);

    for (int k = 0; k < HID; k++) {
        unsigned long long hp[4];
#pragma unroll
        for (int rr = 0; rr < 4; rr++) {
            float h = S.u.hs[r0 + rr][k];
            hp[rr] = pack2(h, h);
        }
#pragma unroll
        for (int q = 0; q < 4; q++) {
            if (q < nc) {
                unsigned long long w = *(const unsigned long long*)&S.Ws2[k][cols[q]];
#pragma unroll
                for (int rr = 0; rr < 4; rr++)
                    acc[rr][q] = ffma2(hp[rr], w, acc[rr][q]);
            }
        }
    }

    // unpack p0 (regs) and stage P1 (smem union over hs)
    float p0[4][4];
    float p1[4][4];
#pragma unroll
    for (int rr = 0; rr < 4; rr++)
#pragma unroll
        for (int q = 0; q < 4; q++)
            if (q < nc) unpack2(acc[rr][q], p0[rr][q], p1[rr][q]);
    __syncthreads();   // everyone done reading hs
#pragma unroll
    for (int rr = 0; rr < 4; rr++)
        for (int q = 0; q < nc; q++)
            S.u.P1[r0 + rr][cols[q]] = p1[rr][q];
    __syncthreads();

    // postmix + MDN head
#pragma unroll
    for (int rr = 0; rr < 4; rr++) {
        int r = r0 + rr;
        int i = r & 15, rb = r & ~15;
        float d = S.sdv[i];
        float av[4]; int ai[4];
#pragma unroll
        for (int q2 = 0; q2 < 4; q2++) { av[q2] = S.sAv[i][q2]; ai[q2] = S.sAi[i][q2]; }
        int row = m0 + r;
        for (int q = 0; q < nc; q++) {
            int c = cols[q];
            float o = d * p0[rr][q] + S.bo[c];
#pragma unroll
            for (int q2 = 0; q2 < 4; q2++)
                o += av[q2] * S.u.P1[rb + ai[q2]][c];
            if (c < 15) {
                out[(size_t)row * 15 + c] = tanhf(o);
            } else if (c < 20) {
                float sg = (o > 0.f) ? (o + 1.f) : expf(o);
                out[(size_t)MROWS * 15 + (size_t)row * 5 + (c - 15)] = fmaxf(sg, 1e-10f);
            } else {
                out[(size_t)MROWS * 20 + (size_t)row * 5 + (c - 20)] = o;
            }
        }
    }
}

extern "C" void kernel_launch(void* const* d_in, const int* in_sizes, int n_in,
                              void* d_out, int out_size) {
    const float* x      = (const float*)d_in[0];
    const float* W_in   = (const float*)d_in[1];
    const float* e_in   = (const float*)d_in[2];
    const float* b_in   = (const float*)d_in[3];
    const float* bn_in  = (const float*)d_in[4];
    const float* W_mid  = (const float*)d_in[5];
    const float* e_mid  = (const float*)d_in[6];
    const float* b_mid  = (const float*)d_in[7];
    const float* bn_mid = (const float*)d_in[8];
    const float* W_out  = (const float*)d_in[9];
    const float* e_out  = (const float*)d_in[10];
    const float* b_out  = (const float*)d_in[11];
    float* out = (float*)d_out;

    static int smem_set = 0;
    if (!smem_set) {
        cudaFuncSetAttribute(mid_mma, cudaFuncAttributeMaxDynamicSharedMemorySize,
                             (int)sizeof(MidSm));
        cudaFuncSetAttribute(out_kernel, cudaFuncAttributeMaxDynamicSharedMemorySize,
                             (int)sizeof(OutSm));
        smem_set = 1;
    }

    prep_kernel<<<1, 256>>>(e_in, bn_in, b_in, e_mid, bn_mid, b_mid, e_out);
    wprep_kernel<<<512, 256>>>(W_mid);
    in_kernel<<<2048, 256>>>(x, W_in);

    const int nblk = MROWS / 128;
    const size_t smb = sizeof(MidSm);
    __half* bfh = nullptr;
    cudaGetSymbolAddress((void**)&bfh, g_Bfrag);
    float *gh = nullptr, *gt = nullptr;
    cudaGetSymbolAddress((void**)&gh, g_h);
    cudaGetSymbolAddress((void**)&gt, g_t);
    for (int p = 0; p < 4; p++) {
        mid_mma<<<nblk, 256, smb>>>(gh, gt, nullptr, bfh + (size_t)(2 * p) * 65536, 1 + 2 * p);
        mid_mma<<<nblk, 256, smb>>>(gt, gh, gh, bfh + (size_t)(2 * p + 1) * 65536, 2 + 2 * p);
    }
    out_kernel<<<MROWS / 128, 256, sizeof(OutSm)>>>(W_out, b_out, out);
}